// round 14
// baseline (speedup 1.0000x reference)
#include <cuda_runtime.h>
#include <cuda_fp16.h>
#include <cstdint>

// out = residual + s * HS @ (w_up w2 w1 w_down)^T
// Associative refold (parallel precompute):
//   wB = w_up @ w2   [2048,512]   (independent)
//   wC = w1 @ w_down [512,2048]   (independent)  -> ONE dual launch
//   o   = HS @ wC^T              (CTA 128x256, A fp32->fp16 in-loader)
//   out = res + s*(o @ wB^T)     (CTA 128x128, BK=64, 2 CTA/SM)
// All GEMMs: C = A*B^T, K contiguous both sides. fp16 HMMA, fp32 accum.

#define M_TOTAL 8192
#define H_Q 2048
#define H_S 512

typedef __half hf;

// ---- device scratch ----
__device__ hf g_wup_h[H_Q * H_S];    // w_up fp16 (A of wB)
__device__ hf g_w1_h[H_S * H_S];     // w1 fp16 (A of wC)
__device__ hf g_w2T_h[H_S * H_S];    // w2^T fp16 (B of wB)
__device__ hf g_wdT_h[H_Q * H_S];    // w_down^T fp16 (B of wC)
__device__ hf g_wB_h[H_Q * H_S];     // w_up@w2
__device__ hf g_wC_h[H_S * H_Q];     // w1@w_down
__device__ hf g_o_h[M_TOTAL * H_S];

// ---------------- helpers ----------------
static __device__ __forceinline__ uint32_t s2u(const void* p) {
    uint32_t a;
    asm("{ .reg .u64 t; cvta.to.shared.u64 t, %1; cvt.u32.u64 %0, t; }"
        : "=r"(a) : "l"(p));
    return a;
}
static __device__ __forceinline__ void cp16(uint32_t s, const void* g) {
    asm volatile("cp.async.cg.shared.global [%0], [%1], 16;" :: "r"(s), "l"(g));
}
static __device__ __forceinline__ void ldm_x4(uint32_t* r, uint32_t addr) {
    asm volatile("ldmatrix.sync.aligned.m8n8.x4.shared.b16 {%0,%1,%2,%3}, [%4];"
                 : "=r"(r[0]), "=r"(r[1]), "=r"(r[2]), "=r"(r[3]) : "r"(addr));
}
static __device__ __forceinline__ void mma_f16(float* c, const uint32_t* a,
                                               const uint32_t* b) {
    asm volatile(
        "mma.sync.aligned.m16n8k16.row.col.f32.f16.f16.f32 "
        "{%0,%1,%2,%3}, {%4,%5,%6,%7}, {%8,%9}, {%0,%1,%2,%3};"
        : "+f"(c[0]), "+f"(c[1]), "+f"(c[2]), "+f"(c[3])
        : "r"(a[0]), "r"(a[1]), "r"(a[2]), "r"(a[3]), "r"(b[0]), "r"(b[1]));
}
static __device__ __forceinline__ uint32_t pack_hf(float a, float b) {
    __half2 p = __floats2half2_rn(a, b);
    return *reinterpret_cast<uint32_t*>(&p);
}

// ---------------- prep: transposes + converts ----------------
// blocks 0..255:     w2 -> w2T fp16 (32x32 tiles)
// blocks 256..1279:  w_down -> wdT fp16
// blocks 1280..2303: w_up -> fp16
// blocks 2304..2559: w1 -> fp16
__global__ __launch_bounds__(256) void prep_all(
    const float* w2, hf* w2T_h,
    const float* wd, hf* wdT_h,
    const float4* wu, __half2* wu_h,
    const float4* w1, __half2* w1_h)
{
    __shared__ float s[32][33];
    int b = blockIdx.x;
    int tid = threadIdx.x;
    if (b < 1280) {
        const float* in; hf* o; int R, C, bx, by;
        if (b < 256) { in = w2; o = w2T_h; R = 512; C = 512;
                       bx = b & 15; by = b >> 4; }
        else         { in = wd; o = wdT_h; R = 512; C = 2048;
                       b -= 256; bx = b & 63; by = b >> 6; }
        int tx = tid & 31, ty = tid >> 5;
#pragma unroll
        for (int j = 0; j < 4; j++)
            s[ty + j * 8][tx] = in[(size_t)(by * 32 + ty + j * 8) * C + bx * 32 + tx];
        __syncthreads();
#pragma unroll
        for (int j = 0; j < 4; j++) {
            size_t off = (size_t)(bx * 32 + ty + j * 8) * R + by * 32 + tx;
            o[off] = __float2half_rn(s[tx][ty + j * 8]);
        }
    } else {
        const float4* src; __half2* dst; int i;
        if (b < 2304) { src = wu; dst = wu_h; i = (b - 1280) * 256 + tid; }
        else          { src = w1; dst = w1_h; i = (b - 2304) * 256 + tid; }
        float4 v = src[i];
        dst[i * 2 + 0] = __floats2half2_rn(v.x, v.y);
        dst[i * 2 + 1] = __floats2half2_rn(v.z, v.w);
    }
}

// ---------------- fp16 HMMA GEMM core (fp32 accum) ----------------
// WM x WN warps, warp tile (MI*16)x(NI*8); CTA BM x BN; BK = 32*CK,
// smem rows padded to BK*2+16 bytes. B: S-stage cp.async. A: AF32 ->
// fp32 LDG+cvt+STS double-buffered (needs BM=128, 256 thr, CK=1);
// else cp.async S-stage. MODE 1: Cf = residual + scale*C. MODE 2: C -> fp16.

template <int MI, int NI, int WM, int WN, int S, int MODE, int AF32, int CK>
static __device__ __forceinline__ void gemm_core(
    const hf* __restrict__ A, const float* __restrict__ Af,
    const hf* __restrict__ B,
    int N, int K,
    hf* __restrict__ Ch, float* __restrict__ Cf,
    const float* __restrict__ residual, const float* __restrict__ scale_p,
    int bm, int bn, char* smem)
{
    constexpr int NTHR = 32 * WM * WN;
    constexpr int BM = WM * MI * 16;
    constexpr int BN = WN * NI * 8;
    constexpr int BK = 32 * CK;
    constexpr int ROWBV = BK * 2 + 16;
    constexpr int CPR = BK / 8;
    constexpr int TA_B = BM * ROWBV;
    constexpr int TB_B = BN * ROWBV;
    constexpr int ASTG = AF32 ? 2 : S;
    constexpr int NCHB = BN * CPR / NTHR;
    constexpr int NCHA = BM * CPR / NTHR;
    static_assert(!AF32 || (BM == 128 && NTHR == 256 && CK == 1), "AF32 shape");

    const uint32_t sb = s2u(smem);
    const uint32_t offB0 = (uint32_t)(ASTG * TA_B);
    const int tid = threadIdx.x;
    const int lane = tid & 31, wid = tid >> 5;
    const int wm = wid % WM, wn = wid / WM;

    const hf* srcA = AF32 ? nullptr : (A + (size_t)bm * K);
    const float* srcAf = AF32 ? (Af + (size_t)bm * K) : nullptr;
    const hf* srcB = B + (size_t)bn * K;

    float acc[MI][NI][4];
#pragma unroll
    for (int i = 0; i < MI; i++)
#pragma unroll
        for (int j = 0; j < NI; j++)
#pragma unroll
            for (int q = 0; q < 4; q++) acc[i][j][q] = 0.0f;

    const int nk = K / BK;

    auto issueB = [&](int kc) {
        const int k0 = kc * BK;
        const uint32_t base = sb + offB0 + (uint32_t)(kc % S) * TB_B;
#pragma unroll
        for (int it = 0; it < NCHB; it++) {
            const int c = tid + it * NTHR;
            const int row = c / CPR, col = c % CPR;
            cp16(base + row * ROWBV + col * 16,
                 srcB + (size_t)row * K + k0 + col * 8);
        }
    };
    auto issueA_cp = [&](int kc) {
        const int k0 = kc * BK;
        const uint32_t base = sb + (uint32_t)(kc % S) * TA_B;
#pragma unroll
        for (int it = 0; it < NCHA; it++) {
            const int c = tid + it * NTHR;
            const int row = c / CPR, col = c % CPR;
            cp16(base + row * ROWBV + col * 16,
                 srcA + (size_t)row * K + k0 + col * 8);
        }
    };

    float4 areg[2][2];
    auto ldgA = [&](int kc) {
        if (!AF32 || kc >= nk) return;
        const int k0 = kc << 5;
#pragma unroll
        for (int t2 = 0; t2 < 2; t2++) {
            const int q = tid + t2 * NTHR;
            const int row = q >> 2, cg = q & 3;
            const float* p = srcAf + (size_t)row * K + k0 + cg * 8;
            areg[t2][0] = *reinterpret_cast<const float4*>(p);
            areg[t2][1] = *reinterpret_cast<const float4*>(p + 4);
        }
    };
    auto stsA = [&](int kc) {
        if (!AF32) return;
        char* base = smem + (size_t)(kc & 1) * TA_B;
#pragma unroll
        for (int t2 = 0; t2 < 2; t2++) {
            const int q = tid + t2 * NTHR;
            const int row = q >> 2, cg = q & 3;
            uint4 v;
            v.x = pack_hf(areg[t2][0].x, areg[t2][0].y);
            v.y = pack_hf(areg[t2][0].z, areg[t2][0].w);
            v.z = pack_hf(areg[t2][1].x, areg[t2][1].y);
            v.w = pack_hf(areg[t2][1].z, areg[t2][1].w);
            *reinterpret_cast<uint4*>(base + row * ROWBV + cg * 16) = v;
        }
    };

    // ---- prologue ----
    if (AF32) {
        ldgA(0);
        stsA(0);
        ldgA(1);
#pragma unroll
        for (int i = 0; i < S - 1; i++) {
            if (i < nk) issueB(i);
            asm volatile("cp.async.commit_group;" ::: "memory");
        }
    } else {
#pragma unroll
        for (int i = 0; i < S - 1; i++) {
            if (i < nk) { issueA_cp(i); issueB(i); }
            asm volatile("cp.async.commit_group;" ::: "memory");
        }
    }

    for (int kc = 0; kc < nk; kc++) {
        asm volatile("cp.async.wait_group %0;" :: "n"(S - 2) : "memory");
        __syncthreads();
        if (AF32 && kc + 1 < nk) { stsA(kc + 1); ldgA(kc + 2); }
        if (kc + S - 1 < nk) {
            if (!AF32) issueA_cp(kc + S - 1);
            issueB(kc + S - 1);
        }
        asm volatile("cp.async.commit_group;" ::: "memory");

        const uint32_t stA = sb + (uint32_t)((AF32 ? (kc & 1) : (kc % S)) * TA_B);
        const uint32_t stB = sb + offB0 + (uint32_t)(kc % S) * TB_B;
#pragma unroll
        for (int ks = 0; ks < 2 * CK; ks++) {
            uint32_t ah[MI][4], bb[NI / 2][4];
            const uint32_t aoff = (uint32_t)((wm * MI * 16 + (lane & 15)) * ROWBV +
                                             ks * 32 + ((lane >> 4) & 1) * 16);
            const uint32_t boff = (uint32_t)((wn * NI * 8 + ((lane >> 4) & 1) * 8 +
                                              (lane & 7)) * ROWBV +
                                             ks * 32 + ((lane >> 3) & 1) * 16);
#pragma unroll
            for (int mi = 0; mi < MI; mi++)
                ldm_x4(ah[mi], stA + aoff + mi * 16 * ROWBV);
#pragma unroll
            for (int nj = 0; nj < NI / 2; nj++)
                ldm_x4(bb[nj], stB + boff + nj * 16 * ROWBV);
#pragma unroll
            for (int ni = 0; ni < NI; ni++)
#pragma unroll
                for (int mi = 0; mi < MI; mi++)
                    mma_f16(acc[mi][ni], ah[mi], &bb[ni >> 1][2 * (ni & 1)]);
        }
    }

    // ---- epilogue ----
    const float sc = (MODE == 1) ? *scale_p : 0.0f;
    const int er = lane >> 2, ec = 2 * (lane & 3);
#pragma unroll
    for (int mi = 0; mi < MI; mi++)
#pragma unroll
        for (int ni = 0; ni < NI; ni++) {
            const float* a4 = acc[mi][ni];
            const int m0 = bm + wm * MI * 16 + mi * 16 + er;
            const int n0 = bn + wn * NI * 8 + ni * 8 + ec;
#pragma unroll
            for (int h = 0; h < 2; h++) {
                const size_t off = (size_t)(m0 + 8 * h) * N + n0;
                if (MODE == 2) {
                    *reinterpret_cast<__half2*>(Ch + off) =
                        __floats2half2_rn(a4[2 * h + 0], a4[2 * h + 1]);
                } else {
                    float2 r = *reinterpret_cast<const float2*>(residual + off);
                    float2 o;
                    o.x = r.x + sc * a4[2 * h + 0];
                    o.y = r.y + sc * a4[2 * h + 1];
                    *reinterpret_cast<float2*>(Cf + off) = o;
                }
            }
        }
}

// ---------------- standard single-GEMM wrapper ----------------
template <int MI, int NI, int WM, int WN, int S, int MODE, int OCC, int AF32, int CK>
__global__ __launch_bounds__(32 * WM * WN, OCC) void gemm_mma(
    const hf* __restrict__ A, const float* __restrict__ Af,
    const hf* __restrict__ B,
    int N, int K,
    hf* __restrict__ Ch, float* __restrict__ Cf,
    const float* __restrict__ residual, const float* __restrict__ scale_p)
{
    extern __shared__ char smem[];
    constexpr int BM = WM * MI * 16;
    constexpr int BN = WN * NI * 8;
    gemm_core<MI, NI, WM, WN, S, MODE, AF32, CK>(
        A, Af, B, N, K, Ch, Cf, residual, scale_p,
        blockIdx.y * BM, blockIdx.x * BN, smem);
}

// ---------------- dual small GEMM: wB and wC in one launch ----------------
// Config: MI=1, NI=4, WM=2, WN=2 -> CTA 32x64, 128 thr, S=6, BK=32, fp16 out.
// blocks [0, 512):   wB = w_up @ w2^T-form: M=2048, N=512 -> 64 x 8 tiles
// blocks [512,1024): wC = w1 @ wd^T-form:   M=512, N=2048 -> 16 x 32 tiles
__global__ __launch_bounds__(128, 4) void gemm_dual(
    const hf* __restrict__ Awb, const hf* __restrict__ Bwb, hf* __restrict__ Cwb,
    const hf* __restrict__ Awc, const hf* __restrict__ Bwc, hf* __restrict__ Cwc)
{
    extern __shared__ char smem[];
    int b = blockIdx.x;
    if (b < 512) {
        // wB: M=2048 (rows of w_up), N=512; tiles: 64 rows x 8 cols
        const int bm = (b >> 3) * 32, bn = (b & 7) * 64;
        gemm_core<1, 4, 2, 2, 6, 2, 0, 1>(
            Awb, nullptr, Bwb, 512, 512, Cwb, nullptr, nullptr, nullptr,
            bm, bn, smem);
    } else {
        b -= 512;
        // wC: M=512, N=2048; tiles: 16 rows x 32 cols
        const int bm = (b & 15) * 32, bn = (b >> 4) * 64;
        gemm_core<1, 4, 2, 2, 6, 2, 0, 1>(
            Awc, nullptr, Bwc, 2048, 512, Cwc, nullptr, nullptr, nullptr,
            bm, bn, smem);
    }
}

// smem sizes
#define SMEM_G4 (2 * 128 * 80 + 4 * 256 * 80)   // GEMM4: 102400
#define SMEM_G5 (6 * 128 * 144)                 // GEMM5: BK=64, S=3 -> 110592
#define SMEM_SM (6 * 32 * 80 + 6 * 64 * 80)     // dual small: 46080

// ---------------- host ----------------
extern "C" void kernel_launch(void* const* d_in, const int* in_sizes, int n_in,
                              void* d_out, int out_size) {
    const float* hs     = (const float*)d_in[0];
    const float* w_down = (const float*)d_in[1];
    const float* w_up   = (const float*)d_in[2];
    const float* w1     = (const float*)d_in[3];
    const float* w2     = (const float*)d_in[4];
    const float* scale  = (const float*)d_in[5];
    float* out          = (float*)d_out;

#define SYM(p, s) cudaGetSymbolAddress((void**)&p, s)
    hf *wu_h, *w1_h, *w2T_h, *wdT_h, *wB_h, *wC_h, *o_h;
    SYM(wu_h, g_wup_h); SYM(w1_h, g_w1_h);
    SYM(w2T_h, g_w2T_h); SYM(wdT_h, g_wdT_h);
    SYM(wB_h, g_wB_h);  SYM(wC_h, g_wC_h);
    SYM(o_h, g_o_h);
#undef SYM

    // GEMM4: CTA 128x256, warp 64x64, AF32 loader, BK=32, OCC1
    cudaFuncSetAttribute((const void*)gemm_mma<4, 8, 2, 4, 4, 2, 1, 1, 1>,
                         cudaFuncAttributeMaxDynamicSharedMemorySize, SMEM_G4);
    // GEMM5: CTA 128x128, warp 64x32, BK=64, S=3, OCC2
    cudaFuncSetAttribute((const void*)gemm_mma<4, 4, 2, 4, 3, 1, 2, 0, 2>,
                         cudaFuncAttributeMaxDynamicSharedMemorySize, SMEM_G5);
    // dual small
    cudaFuncSetAttribute((const void*)gemm_dual,
                         cudaFuncAttributeMaxDynamicSharedMemorySize, SMEM_SM);

    // 0: prep (transposes w2/w_down, converts w_up/w1)
    prep_all<<<2560, 256>>>(w2, w2T_h, w_down, wdT_h,
                            (const float4*)w_up, (__half2*)wu_h,
                            (const float4*)w1, (__half2*)w1_h);

    // 1: dual precompute — wB = w_up@w2, wC = w1@w_down (independent halves)
    gemm_dual<<<1024, 128, SMEM_SM>>>(wu_h, w2T_h, wB_h, w1_h, wdT_h, wC_h);

    // 2: o = hs @ wC^T  (M=8192, N=512, K=2048; A converted in-loader)
    gemm_mma<4, 8, 2, 4, 4, 2, 1, 1, 1><<<dim3(2, 64), 256, SMEM_G4>>>(
        nullptr, hs, wC_h, 512, 2048, o_h, nullptr, nullptr, nullptr);

    // 3: out = res + s * (o @ wB^T)  (M=8192, N=2048, K=512; BK=64)
    gemm_mma<4, 4, 2, 4, 3, 1, 2, 0, 2><<<dim3(16, 64), 256, SMEM_G5>>>(
        o_h, nullptr, wB_h, 2048, 512, nullptr, out, hs, scale);
}

// round 15
// speedup vs baseline: 1.0012x; 1.0012x over previous
#include <cuda_runtime.h>
#include <cuda_fp16.h>
#include <cstdint>

// out = residual + s * HS @ (w_up w2 w1 w_down)^T
// Parallel refold in ONE kernel (fp32 in, fp16 out, transpose via ldmatrix.trans):
//   wB = w_up @ w2   [2048,512]
//   wC = w1 @ w_down [512,2048]
// then:
//   o   = HS @ wC^T              (CTA 128x256, A fp32->fp16 in-loader)
//   out = res + s*(o @ wB^T)     (CTA 128x128, BK=64, 2 CTA/SM)
// 3 launches total. fp16 HMMA, fp32 accumulation.

#define M_TOTAL 8192
#define H_Q 2048
#define H_S 512

typedef __half hf;

// ---- device scratch ----
__device__ hf g_wB_h[H_Q * H_S];     // w_up@w2
__device__ hf g_wC_h[H_S * H_Q];     // w1@w_down
__device__ hf g_o_h[M_TOTAL * H_S];

// ---------------- helpers ----------------
static __device__ __forceinline__ uint32_t s2u(const void* p) {
    uint32_t a;
    asm("{ .reg .u64 t; cvta.to.shared.u64 t, %1; cvt.u32.u64 %0, t; }"
        : "=r"(a) : "l"(p));
    return a;
}
static __device__ __forceinline__ void cp16(uint32_t s, const void* g) {
    asm volatile("cp.async.cg.shared.global [%0], [%1], 16;" :: "r"(s), "l"(g));
}
static __device__ __forceinline__ void ldm_x4(uint32_t* r, uint32_t addr) {
    asm volatile("ldmatrix.sync.aligned.m8n8.x4.shared.b16 {%0,%1,%2,%3}, [%4];"
                 : "=r"(r[0]), "=r"(r[1]), "=r"(r[2]), "=r"(r[3]) : "r"(addr));
}
static __device__ __forceinline__ void ldm_x4t(uint32_t* r, uint32_t addr) {
    asm volatile("ldmatrix.sync.aligned.m8n8.x4.trans.shared.b16 {%0,%1,%2,%3}, [%4];"
                 : "=r"(r[0]), "=r"(r[1]), "=r"(r[2]), "=r"(r[3]) : "r"(addr));
}
static __device__ __forceinline__ void mma_f16(float* c, const uint32_t* a,
                                               const uint32_t* b) {
    asm volatile(
        "mma.sync.aligned.m16n8k16.row.col.f32.f16.f16.f32 "
        "{%0,%1,%2,%3}, {%4,%5,%6,%7}, {%8,%9}, {%0,%1,%2,%3};"
        : "+f"(c[0]), "+f"(c[1]), "+f"(c[2]), "+f"(c[3])
        : "r"(a[0]), "r"(a[1]), "r"(a[2]), "r"(a[3]), "r"(b[0]), "r"(b[1]));
}
static __device__ __forceinline__ uint32_t pack_hf(float a, float b) {
    __half2 p = __floats2half2_rn(a, b);
    return *reinterpret_cast<uint32_t*>(&p);
}

// ---------------- dual weight-fold GEMM (fp32 in, fp16 out) ----------------
// blocks [0,512):    wB = w_up @ w2   (M=2048, N=512,  K=512)
// blocks [512,1024): wC = w1 @ w_down (M=512,  N=2048, K=512)
// CTA 32x64, 4 warps (2x2), warp 16x32. BK=32, nk=16.
// A: [M,K] fp32, m-major smem tile (80B rows), normal ldmatrix.
// B: [K,N] fp32, k-major smem tile (144B rows), ldmatrix.trans.
// Both loaded via fp32 LDG -> reg double-buffer -> cvt -> STS.
#define DA_STG 2560            // 32 rows * 80 B
#define DB_STG 4608            // 32 rows * 144 B

__global__ __launch_bounds__(128, 8) void gemm_dual(
    const float* __restrict__ wu, const float* __restrict__ w2, hf* __restrict__ wB,
    const float* __restrict__ w1, const float* __restrict__ wd, hf* __restrict__ wC)
{
    __shared__ char smem[2 * DA_STG + 2 * DB_STG];
    const int tid = threadIdx.x;
    const int lane = tid & 31, wid = tid >> 5;
    const int wm = wid & 1, wn = wid >> 1;

    const float *A, *B; hf* C;
    int ldB, Nn, bm, bn;
    int b = blockIdx.x;
    if (b < 512) {
        A = wu; B = w2; C = wB; ldB = 512; Nn = 512;
        bm = (b >> 3) * 32; bn = (b & 7) * 64;
    } else {
        b -= 512;
        A = w1; B = wd; C = wC; ldB = 2048; Nn = 2048;
        bm = (b & 15) * 32; bn = (b >> 4) * 64;
    }
    const int K = 512, nk = 16;

    const uint32_t sbA = s2u(smem);
    const uint32_t sbB = sbA + 2 * DA_STG;

    float4 ra[2], rb[4];
    auto ldgAB = [&](int kc) {
        if (kc >= nk) return;
        const int k0 = kc * 32;
#pragma unroll
        for (int t = 0; t < 2; t++) {           // A: 32 rows x 8 float4
            const int c = tid + t * 128;
            const int row = c >> 3, col = c & 7;
            ra[t] = *reinterpret_cast<const float4*>(
                A + (size_t)(bm + row) * K + k0 + col * 4);
        }
#pragma unroll
        for (int t = 0; t < 4; t++) {           // B: 32 k-rows x 16 float4
            const int c = tid + t * 128;
            const int row = c >> 4, col = c & 15;
            rb[t] = *reinterpret_cast<const float4*>(
                B + (size_t)(k0 + row) * ldB + bn + col * 4);
        }
    };
    auto stsAB = [&](int kc) {
        char* pa = smem + (kc & 1) * DA_STG;
        char* pb = smem + 2 * DA_STG + (kc & 1) * DB_STG;
#pragma unroll
        for (int t = 0; t < 2; t++) {
            const int c = tid + t * 128;
            const int row = c >> 3, col = c & 7;
            uint2 v = make_uint2(pack_hf(ra[t].x, ra[t].y), pack_hf(ra[t].z, ra[t].w));
            *reinterpret_cast<uint2*>(pa + row * 80 + col * 8) = v;
        }
#pragma unroll
        for (int t = 0; t < 4; t++) {
            const int c = tid + t * 128;
            const int row = c >> 4, col = c & 15;
            uint2 v = make_uint2(pack_hf(rb[t].x, rb[t].y), pack_hf(rb[t].z, rb[t].w));
            *reinterpret_cast<uint2*>(pb + row * 144 + col * 8) = v;
        }
    };

    float acc[4][4];
#pragma unroll
    for (int i = 0; i < 4; i++)
#pragma unroll
        for (int q = 0; q < 4; q++) acc[i][q] = 0.0f;

    ldgAB(0);
    stsAB(0);
    ldgAB(1);

    for (int kc = 0; kc < nk; kc++) {
        __syncthreads();
        if (kc + 1 < nk) { stsAB(kc + 1); ldgAB(kc + 2); }

        const uint32_t stA = sbA + (uint32_t)((kc & 1) * DA_STG);
        const uint32_t stB = sbB + (uint32_t)((kc & 1) * DB_STG);
#pragma unroll
        for (int ks = 0; ks < 2; ks++) {
            uint32_t a[4], b0[4], b1[4];
            ldm_x4(a, stA + (wm * 16 + (lane & 15)) * 80 + ks * 32 +
                          ((lane >> 4) & 1) * 16);
            // trans B: lanes address k-rows; matrices: (k-lo/hi) x (n 8-groups)
            const uint32_t bt = stB +
                (uint32_t)((ks * 16 + (lane & 7) + ((lane >> 3) & 1) * 8) * 144 +
                           (wn * 32 + ((lane >> 4) & 1) * 8) * 2);
            ldm_x4t(b0, bt);
            ldm_x4t(b1, bt + 32);   // +16 n-cols * 2B
            mma_f16(acc[0], a, b0 + 0);
            mma_f16(acc[1], a, b0 + 2);
            mma_f16(acc[2], a, b1 + 0);
            mma_f16(acc[3], a, b1 + 2);
        }
    }

    const int er = lane >> 2, ec = 2 * (lane & 3);
#pragma unroll
    for (int ni = 0; ni < 4; ni++) {
        const int n0 = bn + wn * 32 + ni * 8 + ec;
#pragma unroll
        for (int h = 0; h < 2; h++) {
            const int m0 = bm + wm * 16 + er + 8 * h;
            *reinterpret_cast<__half2*>(C + (size_t)m0 * Nn + n0) =
                __floats2half2_rn(acc[ni][2 * h + 0], acc[ni][2 * h + 1]);
        }
    }
}

// ---------------- fp16 HMMA GEMM (fp32 accum) — proven big-GEMM core ----------------
// WM x WN warps, warp tile (MI*16)x(NI*8); CTA BM x BN; BK = 32*CK,
// smem rows padded to BK*2+16 bytes. B: S-stage cp.async. A: AF32 ->
// fp32 LDG+cvt+STS double-buffered (needs BM=128, 256 thr, CK=1);
// else cp.async S-stage. MODE 1: Cf = residual + scale*C. MODE 2: C -> fp16.

template <int MI, int NI, int WM, int WN, int S, int MODE, int OCC, int AF32, int CK>
__global__ __launch_bounds__(32 * WM * WN, OCC) void gemm_mma(
    const hf* __restrict__ A, const float* __restrict__ Af,
    const hf* __restrict__ B,
    int N, int K,
    hf* __restrict__ Ch, float* __restrict__ Cf,
    const float* __restrict__ residual, const float* __restrict__ scale_p)
{
    constexpr int NTHR = 32 * WM * WN;
    constexpr int BM = WM * MI * 16;
    constexpr int BN = WN * NI * 8;
    constexpr int BK = 32 * CK;
    constexpr int ROWBV = BK * 2 + 16;
    constexpr int CPR = BK / 8;
    constexpr int TA_B = BM * ROWBV;
    constexpr int TB_B = BN * ROWBV;
    constexpr int ASTG = AF32 ? 2 : S;
    constexpr int NCHB = BN * CPR / NTHR;
    constexpr int NCHA = BM * CPR / NTHR;
    static_assert(!AF32 || (BM == 128 && NTHR == 256 && CK == 1), "AF32 shape");

    extern __shared__ char smem[];
    const uint32_t sb = s2u(smem);
    const uint32_t offB0 = (uint32_t)(ASTG * TA_B);
    const int tid = threadIdx.x;
    const int lane = tid & 31, wid = tid >> 5;
    const int wm = wid % WM, wn = wid / WM;
    const int bm = blockIdx.y * BM, bn = blockIdx.x * BN;

    const hf* srcA = AF32 ? nullptr : (A + (size_t)bm * K);
    const float* srcAf = AF32 ? (Af + (size_t)bm * K) : nullptr;
    const hf* srcB = B + (size_t)bn * K;

    float acc[MI][NI][4];
#pragma unroll
    for (int i = 0; i < MI; i++)
#pragma unroll
        for (int j = 0; j < NI; j++)
#pragma unroll
            for (int q = 0; q < 4; q++) acc[i][j][q] = 0.0f;

    const int nk = K / BK;

    auto issueB = [&](int kc) {
        const int k0 = kc * BK;
        const uint32_t base = sb + offB0 + (uint32_t)(kc % S) * TB_B;
#pragma unroll
        for (int it = 0; it < NCHB; it++) {
            const int c = tid + it * NTHR;
            const int row = c / CPR, col = c % CPR;
            cp16(base + row * ROWBV + col * 16,
                 srcB + (size_t)row * K + k0 + col * 8);
        }
    };
    auto issueA_cp = [&](int kc) {
        const int k0 = kc * BK;
        const uint32_t base = sb + (uint32_t)(kc % S) * TA_B;
#pragma unroll
        for (int it = 0; it < NCHA; it++) {
            const int c = tid + it * NTHR;
            const int row = c / CPR, col = c % CPR;
            cp16(base + row * ROWBV + col * 16,
                 srcA + (size_t)row * K + k0 + col * 8);
        }
    };

    float4 areg[2][2];
    auto ldgA = [&](int kc) {
        if (!AF32 || kc >= nk) return;
        const int k0 = kc << 5;
#pragma unroll
        for (int t2 = 0; t2 < 2; t2++) {
            const int q = tid + t2 * NTHR;
            const int row = q >> 2, cg = q & 3;
            const float* p = srcAf + (size_t)row * K + k0 + cg * 8;
            areg[t2][0] = *reinterpret_cast<const float4*>(p);
            areg[t2][1] = *reinterpret_cast<const float4*>(p + 4);
        }
    };
    auto stsA = [&](int kc) {
        if (!AF32) return;
        char* base = smem + (size_t)(kc & 1) * TA_B;
#pragma unroll
        for (int t2 = 0; t2 < 2; t2++) {
            const int q = tid + t2 * NTHR;
            const int row = q >> 2, cg = q & 3;
            uint4 v;
            v.x = pack_hf(areg[t2][0].x, areg[t2][0].y);
            v.y = pack_hf(areg[t2][0].z, areg[t2][0].w);
            v.z = pack_hf(areg[t2][1].x, areg[t2][1].y);
            v.w = pack_hf(areg[t2][1].z, areg[t2][1].w);
            *reinterpret_cast<uint4*>(base + row * ROWBV + cg * 16) = v;
        }
    };

    // ---- prologue ----
    if (AF32) {
        ldgA(0);
        stsA(0);
        ldgA(1);
#pragma unroll
        for (int i = 0; i < S - 1; i++) {
            if (i < nk) issueB(i);
            asm volatile("cp.async.commit_group;" ::: "memory");
        }
    } else {
#pragma unroll
        for (int i = 0; i < S - 1; i++) {
            if (i < nk) { issueA_cp(i); issueB(i); }
            asm volatile("cp.async.commit_group;" ::: "memory");
        }
    }

    for (int kc = 0; kc < nk; kc++) {
        asm volatile("cp.async.wait_group %0;" :: "n"(S - 2) : "memory");
        __syncthreads();
        if (AF32 && kc + 1 < nk) { stsA(kc + 1); ldgA(kc + 2); }
        if (kc + S - 1 < nk) {
            if (!AF32) issueA_cp(kc + S - 1);
            issueB(kc + S - 1);
        }
        asm volatile("cp.async.commit_group;" ::: "memory");

        const uint32_t stA = sb + (uint32_t)((AF32 ? (kc & 1) : (kc % S)) * TA_B);
        const uint32_t stB = sb + offB0 + (uint32_t)(kc % S) * TB_B;
#pragma unroll
        for (int ks = 0; ks < 2 * CK; ks++) {
            uint32_t ah[MI][4], bb[NI / 2][4];
            const uint32_t aoff = (uint32_t)((wm * MI * 16 + (lane & 15)) * ROWBV +
                                             ks * 32 + ((lane >> 4) & 1) * 16);
            const uint32_t boff = (uint32_t)((wn * NI * 8 + ((lane >> 4) & 1) * 8 +
                                              (lane & 7)) * ROWBV +
                                             ks * 32 + ((lane >> 3) & 1) * 16);
#pragma unroll
            for (int mi = 0; mi < MI; mi++)
                ldm_x4(ah[mi], stA + aoff + mi * 16 * ROWBV);
#pragma unroll
            for (int nj = 0; nj < NI / 2; nj++)
                ldm_x4(bb[nj], stB + boff + nj * 16 * ROWBV);
#pragma unroll
            for (int ni = 0; ni < NI; ni++)
#pragma unroll
                for (int mi = 0; mi < MI; mi++)
                    mma_f16(acc[mi][ni], ah[mi], &bb[ni >> 1][2 * (ni & 1)]);
        }
    }

    // ---- epilogue ----
    const float sc = (MODE == 1) ? *scale_p : 0.0f;
    const int er = lane >> 2, ec = 2 * (lane & 3);
#pragma unroll
    for (int mi = 0; mi < MI; mi++)
#pragma unroll
        for (int ni = 0; ni < NI; ni++) {
            const float* a4 = acc[mi][ni];
            const int m0 = bm + wm * MI * 16 + mi * 16 + er;
            const int n0 = bn + wn * NI * 8 + ni * 8 + ec;
#pragma unroll
            for (int h = 0; h < 2; h++) {
                const size_t off = (size_t)(m0 + 8 * h) * N + n0;
                if (MODE == 2) {
                    *reinterpret_cast<__half2*>(Ch + off) =
                        __floats2half2_rn(a4[2 * h + 0], a4[2 * h + 1]);
                } else {
                    float2 r = *reinterpret_cast<const float2*>(residual + off);
                    float2 o;
                    o.x = r.x + sc * a4[2 * h + 0];
                    o.y = r.y + sc * a4[2 * h + 1];
                    *reinterpret_cast<float2*>(Cf + off) = o;
                }
            }
        }
}

// smem sizes
#define SMEM_G4 (2 * 128 * 80 + 4 * 256 * 80)   // GEMM4: 102400
#define SMEM_G5 (6 * 128 * 144)                 // GEMM5: BK=64, S=3 -> 110592

// ---------------- host ----------------
extern "C" void kernel_launch(void* const* d_in, const int* in_sizes, int n_in,
                              void* d_out, int out_size) {
    const float* hs     = (const float*)d_in[0];
    const float* w_down = (const float*)d_in[1];
    const float* w_up   = (const float*)d_in[2];
    const float* w1     = (const float*)d_in[3];
    const float* w2     = (const float*)d_in[4];
    const float* scale  = (const float*)d_in[5];
    float* out          = (float*)d_out;

    hf *wB_h, *wC_h, *o_h;
    cudaGetSymbolAddress((void**)&wB_h, g_wB_h);
    cudaGetSymbolAddress((void**)&wC_h, g_wC_h);
    cudaGetSymbolAddress((void**)&o_h, g_o_h);

    // GEMM4: CTA 128x256, warp 64x64, AF32 loader, BK=32, OCC1
    cudaFuncSetAttribute((const void*)gemm_mma<4, 8, 2, 4, 4, 2, 1, 1, 1>,
                         cudaFuncAttributeMaxDynamicSharedMemorySize, SMEM_G4);
    // GEMM5: CTA 128x128, warp 64x32, BK=64, S=3, OCC2
    cudaFuncSetAttribute((const void*)gemm_mma<4, 4, 2, 4, 3, 1, 2, 0, 2>,
                         cudaFuncAttributeMaxDynamicSharedMemorySize, SMEM_G5);

    // 1: dual weight fold — wB = w_up@w2, wC = w1@w_down (fp32 in, fp16 out)
    gemm_dual<<<1024, 128>>>(w_up, w2, wB_h, w1, w_down, wC_h);

    // 2: o = hs @ wC^T  (M=8192, N=512, K=2048; A converted in-loader)
    gemm_mma<4, 8, 2, 4, 4, 2, 1, 1, 1><<<dim3(2, 64), 256, SMEM_G4>>>(
        nullptr, hs, wC_h, 512, 2048, o_h, nullptr, nullptr, nullptr);

    // 3: out = res + s * (o @ wB^T)  (M=8192, N=2048, K=512; BK=64)
    gemm_mma<4, 4, 2, 4, 3, 1, 2, 0, 2><<<dim3(16, 64), 256, SMEM_G5>>>(
        o_h, nullptr, wB_h, 2048, 512, nullptr, out, hs, scale);
}